// round 2
// baseline (speedup 1.0000x reference)
#include <cuda_runtime.h>

#define SEQ   2048
#define EMB   1024
#define NH    16
#define HSZ   64
#define BATCH 2
#define ROWS  (BATCH * SEQ)     // 4096
#define D3    (3 * EMB)         // 3072

// Scratch (device globals — no allocation allowed)
__device__ float g_qkv[ROWS * D3];     // [b*s, 3*EMB]  (q | k | v per row)
__device__ float g_obuf[ROWS * EMB];   // attention output, [b*s, EMB]

// ---------------------------------------------------------------------------
// SGEMM + bias:  C[M,N] = A[M,K] @ B[K,N] + bias[N]
// MODE 0: A = param (x),      C = g_qkv
// MODE 1: A = g_obuf,         C = param (out)
// 128x128 tile, BK=8, 256 threads, 8x8 per thread.
// M % 128 == 0, N % 128 == 0, K % 8 == 0 (all true here).
// ---------------------------------------------------------------------------
template <int MODE>
__global__ __launch_bounds__(256)
void sgemm_bias(const float* __restrict__ Ain,
                const float* __restrict__ B,
                const float* __restrict__ bias,
                float* __restrict__ Cout,
                int M, int N, int K)
{
    const float* A = (MODE == 0) ? Ain : g_obuf;
    float* C       = (MODE == 0) ? g_qkv : Cout;

    __shared__ float As[8][128];   // As[k][m]
    __shared__ float Bs[8][128];   // Bs[k][n]

    const int tid = threadIdx.x;
    const int bx = blockIdx.x, by = blockIdx.y;

    // A tile load mapping: 128x8 floats = 256 float4
    const int a_row = tid >> 1;          // 0..127
    const int a_col = (tid & 1) * 4;     // 0 or 4
    // B tile load mapping: 8x128 floats = 256 float4
    const int b_row = tid >> 5;          // 0..7
    const int b_col = (tid & 31) * 4;

    const int tx = tid & 15;             // 0..15 (cols)
    const int ty = tid >> 4;             // 0..15 (rows)

    const float* Ab = A + (long)(by * 128) * K;
    const float* Bb = B + bx * 128;

    float acc[8][8];
#pragma unroll
    for (int i = 0; i < 8; i++)
#pragma unroll
        for (int j = 0; j < 8; j++) acc[i][j] = 0.f;

    for (int k0 = 0; k0 < K; k0 += 8) {
        float4 av = *(const float4*)(Ab + (long)a_row * K + k0 + a_col);
        float4 bv = *(const float4*)(Bb + (long)(k0 + b_row) * N + b_col);

        As[a_col + 0][a_row] = av.x;
        As[a_col + 1][a_row] = av.y;
        As[a_col + 2][a_row] = av.z;
        As[a_col + 3][a_row] = av.w;
        *(float4*)&Bs[b_row][b_col] = bv;
        __syncthreads();

#pragma unroll
        for (int k = 0; k < 8; k++) {
            float ra[8], rb[8];
            *(float4*)&ra[0] = *(const float4*)&As[k][ty * 8];
            *(float4*)&ra[4] = *(const float4*)&As[k][ty * 8 + 4];
            *(float4*)&rb[0] = *(const float4*)&Bs[k][tx * 8];
            *(float4*)&rb[4] = *(const float4*)&Bs[k][tx * 8 + 4];
#pragma unroll
            for (int i = 0; i < 8; i++)
#pragma unroll
                for (int j = 0; j < 8; j++)
                    acc[i][j] += ra[i] * rb[j];
        }
        __syncthreads();
    }

    // epilogue + bias
#pragma unroll
    for (int i = 0; i < 8; i++) {
        const int row = by * 128 + ty * 8 + i;
#pragma unroll
        for (int j = 0; j < 8; j += 4) {
            const int col = bx * 128 + tx * 8 + j;
            float4 c;
            c.x = acc[i][j + 0] + bias[col + 0];
            c.y = acc[i][j + 1] + bias[col + 1];
            c.z = acc[i][j + 2] + bias[col + 2];
            c.w = acc[i][j + 3] + bias[col + 3];
            *(float4*)&C[(long)row * N + col] = c;
        }
    }
}

// ---------------------------------------------------------------------------
// Flash-attention fp32, causal. 64-row Q tile, 64-col K/V tiles, hs=64.
// Block = 256 threads; thread t: row r = t/4, lane-group cg = t%4.
// Each thread owns 16 score columns (interleaved c = cg + 4j for bank spread)
// and 16 output dims (d = cg*16 + j).
// smem: Q,K,V,P tiles with pitch 68 (row shift of 4 banks -> conflict-free).
// ---------------------------------------------------------------------------
#define PITCH 68
#define SMEM_ATTN (4 * 64 * PITCH * 4)

__global__ __launch_bounds__(256, 2)
void attn_kernel()
{
    extern __shared__ float sm[];
    float* Qs = sm;
    float* Ks = Qs + 64 * PITCH;
    float* Vs = Ks + 64 * PITCH;
    float* Ps = Vs + 64 * PITCH;

    const int qt = blockIdx.x;          // q tile (0..31)
    const int h  = blockIdx.y;          // head
    const int b  = blockIdx.z;          // batch
    const int tid = threadIdx.x;
    const int r  = tid >> 2;            // q row in tile, 0..63
    const int cg = tid & 3;             // column group, 0..3

    const float* base = g_qkv + (long)b * SEQ * D3 + h * HSZ;
    const float* qp = base;             // +0    -> Q
    const float* kp = base + EMB;       // +1024 -> K
    const float* vp = base + 2 * EMB;   // +2048 -> V

    const int q0 = qt * 64;
    const int qg = q0 + r;

    // load Q tile
#pragma unroll
    for (int idx = tid; idx < 64 * 64; idx += 256) {
        int s = idx >> 6, d = idx & 63;
        Qs[s * PITCH + d] = qp[(long)(q0 + s) * D3 + d];
    }

    float m = -1e30f, l = 0.f;
    float acc[16];
#pragma unroll
    for (int j = 0; j < 16; j++) acc[j] = 0.f;

    for (int kt = 0; kt <= qt; kt++) {
        __syncthreads();   // prev PV done (and Q load on first iter)
        // load K,V tiles
        const int k0 = kt * 64;
#pragma unroll
        for (int idx = tid; idx < 64 * 64; idx += 256) {
            int s = idx >> 6, d = idx & 63;
            Ks[s * PITCH + d] = kp[(long)(k0 + s) * D3 + d];
            Vs[s * PITCH + d] = vp[(long)(k0 + s) * D3 + d];
        }
        __syncthreads();

        // scores: sc[j] = Q[r,:] . K[cg+4j,:]   (interleaved columns)
        float sc[16];
#pragma unroll
        for (int j = 0; j < 16; j++) sc[j] = 0.f;
        const float* qrow = Qs + r * PITCH;
#pragma unroll
        for (int i = 0; i < 64; i += 4) {
            float4 q4 = *(const float4*)(qrow + i);
#pragma unroll
            for (int j = 0; j < 16; j++) {
                float4 k4 = *(const float4*)(Ks + (cg + 4 * j) * PITCH + i);
                sc[j] += q4.x * k4.x + q4.y * k4.y + q4.z * k4.z + q4.w * k4.w;
            }
        }

        // scale + causal mask
        float tmax = -1e30f;
#pragma unroll
        for (int j = 0; j < 16; j++) {
            sc[j] *= 0.125f;                       // 1/sqrt(64)
            int kg = k0 + cg + 4 * j;
            if (kt == qt && kg > qg) sc[j] = -1e30f;
            tmax = fmaxf(tmax, sc[j]);
        }
        // row max across the 4-lane group (lanes 4r..4r+3, same warp)
        tmax = fmaxf(tmax, __shfl_xor_sync(0xffffffffu, tmax, 1));
        tmax = fmaxf(tmax, __shfl_xor_sync(0xffffffffu, tmax, 2));
        float mnew = fmaxf(m, tmax);

        float psum = 0.f;
        float* prow = Ps + r * PITCH;
#pragma unroll
        for (int j = 0; j < 16; j++) {
            float p = __expf(sc[j] - mnew);
            psum += p;
            prow[cg + 4 * j] = p;
        }
        psum += __shfl_xor_sync(0xffffffffu, psum, 1);
        psum += __shfl_xor_sync(0xffffffffu, psum, 2);

        float scale = __expf(m - mnew);
        l = l * scale + psum;
        m = mnew;
#pragma unroll
        for (int j = 0; j < 16; j++) acc[j] *= scale;

        __syncwarp();   // P row written by 4 lanes of this warp

        // PV: acc[d] += sum_k P[r,k] * V[k, d],  d = cg*16 + (0..15)
        const float* vbase = Vs + cg * 16;
#pragma unroll 8
        for (int k = 0; k < 64; k++) {
            float p = prow[k];
            const float* vrow = vbase + k * PITCH;
            float4 v0 = *(const float4*)(vrow + 0);
            float4 v1 = *(const float4*)(vrow + 4);
            float4 v2 = *(const float4*)(vrow + 8);
            float4 v3 = *(const float4*)(vrow + 12);
            acc[0]  += p * v0.x;  acc[1]  += p * v0.y;
            acc[2]  += p * v0.z;  acc[3]  += p * v0.w;
            acc[4]  += p * v1.x;  acc[5]  += p * v1.y;
            acc[6]  += p * v1.z;  acc[7]  += p * v1.w;
            acc[8]  += p * v2.x;  acc[9]  += p * v2.y;
            acc[10] += p * v2.z;  acc[11] += p * v2.w;
            acc[12] += p * v3.x;  acc[13] += p * v3.y;
            acc[14] += p * v3.z;  acc[15] += p * v3.w;
        }
    }

    // finalize: O[b, qg, h*64 + d] = acc/l
    const float inv = 1.f / l;
    float* orow = g_obuf + (long)(b * SEQ + qg) * EMB + h * HSZ + cg * 16;
#pragma unroll
    for (int j = 0; j < 16; j += 4) {
        float4 o;
        o.x = acc[j + 0] * inv;
        o.y = acc[j + 1] * inv;
        o.z = acc[j + 2] * inv;
        o.w = acc[j + 3] * inv;
        *(float4*)&orow[j] = o;
    }
}

// ---------------------------------------------------------------------------
extern "C" void kernel_launch(void* const* d_in, const int* in_sizes, int n_in,
                              void* d_out, int out_size)
{
    const float* x     = (const float*)d_in[0];
    const float* W_qkv = (const float*)d_in[1];
    const float* b_qkv = (const float*)d_in[2];
    const float* W_out = (const float*)d_in[3];
    const float* b_out = (const float*)d_in[4];
    float* out = (float*)d_out;

    // 1) QKV projection: g_qkv = x @ W_qkv + b_qkv
    sgemm_bias<0><<<dim3(D3 / 128, ROWS / 128), 256>>>(
        x, W_qkv, b_qkv, nullptr, ROWS, D3, EMB);

    // 2) causal flash attention -> g_obuf
    cudaFuncSetAttribute(attn_kernel,
                         cudaFuncAttributeMaxDynamicSharedMemorySize, SMEM_ATTN);
    attn_kernel<<<dim3(SEQ / 64, NH, BATCH), 256, SMEM_ATTN>>>();

    // 3) output projection: out = g_obuf @ W_out + b_out
    sgemm_bias<1><<<dim3(EMB / 128, ROWS / 128), 256>>>(
        nullptr, W_out, b_out, out, ROWS, EMB, EMB);
}